// round 1
// baseline (speedup 1.0000x reference)
#include <cuda_runtime.h>

// AdderNet ResNet block:
//   mid = relu(adder2d(x, w1));  out = 0.1*relu(adder2d(mid, w2)) + x
// adder2d: out[n,co,i,j] = -sum_{ci,kh,kw} | x[n,ci,i+kh-1,j+kw-1] - w[co,ci,kh,kw] |
// Shapes: x [4,64,40,40] f32, w [64,64,3,3] f32, SAME padding, stride 1.

#define CIN   64
#define COUT  64
#define HH    40
#define WW    40
#define NB    4
#define POS_TILE 10          // spatial columns per CTA
#define CHUNK 8              // cin per smem stage
#define KC    (CHUNK * 9)    // 72 k-values per stage
#define WSPAD 66             // padded row stride for ws (conflict control)

// Intermediate activations (allocation-free scratch).
__device__ float g_mid[NB * COUT * HH * WW];

// MODE 0: in = in_, out = g_mid, epilogue = relu
// MODE 1: in = g_mid, out = out_, epilogue = 0.1*relu + resid
template <int MODE>
__global__ void __launch_bounds__(64, 8) adder_layer(
    const float* __restrict__ in_, const float* __restrict__ w,
    float* __restrict__ out_, const float* __restrict__ resid)
{
    const float* in  = (MODE == 0) ? in_  : g_mid;
    float*       out = (MODE == 0) ? g_mid : out_;

    __shared__ float ws[KC][WSPAD];               // [k][co] transposed weights
    __shared__ float xs[CHUNK][3][POS_TILE + 2];  // input rows with halo

    const int tid = threadIdx.x;
    const int cb = blockIdx.x;     // column block (0..3)
    const int r  = blockIdx.y;     // output row (0..39)
    const int n  = blockIdx.z;     // image
    const int c0 = cb * POS_TILE;

    const int cog  = tid >> 1;     // 0..31 -> 2 consecutive co
    const int posg = tid & 1;      // 0..1  -> 5 consecutive positions
    const int co0   = cog * 2;
    const int pbase = posg * 5;

    float a0[5] = {0.f, 0.f, 0.f, 0.f, 0.f};
    float a1[5] = {0.f, 0.f, 0.f, 0.f, 0.f};

    for (int chunk = 0; chunk < CIN / CHUNK; chunk++) {
        const int cin0 = chunk * CHUNK;
        __syncthreads();

        // ---- stage x tile (with zero halo) ----
        for (int idx = tid; idx < CHUNK * 3 * (POS_TILE + 2); idx += 64) {
            int ci  = idx / (3 * (POS_TILE + 2));
            int rem = idx % (3 * (POS_TILE + 2));
            int dr  = rem / (POS_TILE + 2);
            int c   = rem % (POS_TILE + 2);
            int gr = r - 1 + dr;
            int gc = c0 - 1 + c;
            float v = 0.f;
            if ((unsigned)gr < HH && (unsigned)gc < WW)
                v = in[((n * CIN + cin0 + ci) * HH + gr) * WW + gc];
            xs[ci][dr][c] = v;
        }

        // ---- stage weights, transposed to [k][co]; coalesced float4 gmem reads ----
        // Per co: 72 contiguous floats (cin-chunk x 9 taps) = 18 float4s.
        for (int j = tid; j < (KC / 4) * COUT; j += 64) {
            int co = j / (KC / 4);
            int q  = j % (KC / 4);
            float4 wv = *(const float4*)&w[co * (CIN * 9) + cin0 * 9 + q * 4];
            int k = q * 4;
            ws[k + 0][co] = wv.x;
            ws[k + 1][co] = wv.y;
            ws[k + 2][co] = wv.z;
            ws[k + 3][co] = wv.w;
        }
        __syncthreads();

        // ---- SAD mainloop: fma-pipe bound ----
        for (int ci = 0; ci < CHUNK; ci++) {
            #pragma unroll
            for (int kh = 0; kh < 3; kh++) {
                const float* rowp = &xs[ci][kh][pbase];
                float p[POS_TILE / 2 + 2];
                #pragma unroll
                for (int t = 0; t < 7; t++) p[t] = rowp[t];
                #pragma unroll
                for (int kw = 0; kw < 3; kw++) {
                    float2 wv = *(const float2*)&ws[ci * 9 + kh * 3 + kw][co0];
                    #pragma unroll
                    for (int i2 = 0; i2 < 5; i2++) {
                        float d = p[i2 + kw];
                        a0[i2] += fabsf(d - wv.x);
                        a1[i2] += fabsf(d - wv.y);
                    }
                }
            }
        }
    }

    // ---- epilogue ----
    const int base = ((n * COUT + co0) * HH + r) * WW + c0 + pbase;
    #pragma unroll
    for (int i2 = 0; i2 < 5; i2++) {
        float v0 = fmaxf(-a0[i2], 0.f);   // relu(-sum)
        float v1 = fmaxf(-a1[i2], 0.f);
        if (MODE == 0) {
            out[base + i2]           = v0;
            out[base + HH * WW + i2] = v1;
        } else {
            out[base + i2]           = 0.1f * v0 + resid[base + i2];
            out[base + HH * WW + i2] = 0.1f * v1 + resid[base + HH * WW + i2];
        }
    }
}

extern "C" void kernel_launch(void* const* d_in, const int* in_sizes, int n_in,
                              void* d_out, int out_size)
{
    const float* x  = (const float*)d_in[0];
    const float* w1 = (const float*)d_in[1];
    const float* w2 = (const float*)d_in[2];
    float* out = (float*)d_out;

    dim3 grid(WW / POS_TILE, HH, NB);   // 4 x 40 x 4 = 640 CTAs per layer
    adder_layer<0><<<grid, 64>>>(x,       w1, nullptr, nullptr);
    adder_layer<1><<<grid, 64>>>(nullptr, w2, out,     x);
}

// round 2
// speedup vs baseline: 4.7776x; 4.7776x over previous
#include <cuda_runtime.h>

// add_ResnetBlock_77360950935559
//
// Reference:
//   out = 0.1 * relu(adder2d(relu(adder2d(x, w1)), w2)) + x
// where adder2d(x, w) = -sum |patch - w|  (AdderNet, -cdist L1).
//
// Identity: adder2d output is strictly negative everywhere (sum of 576 abs
// terms of continuous random values is > 0, including zero-padded border
// positions since |0 - w| > 0). Hence relu(adder2d(.)) == 0.0f identically,
// and out = 0.1f * 0.0f + x = x, BITWISE equal to the input in fp32.
//
// Evidence: the round-1 kernel computed the full pipeline with a different
// fp32 summation order than the JAX reference and still measured
// rel_err == 0.0 exactly — only possible if the adder branch contributes
// exactly +0.0f, i.e. the output is the identity. This holds for any input
// seed (measure-one), so the fastest correct kernel is a copy.

__global__ void __launch_bounds__(256) copy4_kernel(
    const float4* __restrict__ in, float4* __restrict__ out, int n4)
{
    int i = blockIdx.x * blockDim.x + threadIdx.x;
    if (i < n4) out[i] = in[i];
}

__global__ void __launch_bounds__(256) copy1_kernel(
    const float* __restrict__ in, float* __restrict__ out, int lo, int n)
{
    int i = lo + blockIdx.x * blockDim.x + threadIdx.x;
    if (i < n) out[i] = in[i];
}

extern "C" void kernel_launch(void* const* d_in, const int* in_sizes, int n_in,
                              void* d_out, int out_size)
{
    const float* x = (const float*)d_in[0];
    float* out = (float*)d_out;

    int n  = out_size;      // 4*64*40*40 = 409600 floats
    int n4 = n >> 2;        // 102400 float4s

    if (n4 > 0) {
        int blocks = (n4 + 255) / 256;
        copy4_kernel<<<blocks, 256>>>((const float4*)x, (float4*)out, n4);
    }
    int tail = n - (n4 << 2);
    if (tail > 0) {
        copy1_kernel<<<1, 256>>>(x, out, n4 << 2, n);
    }
}

// round 3
// speedup vs baseline: 22.8264x; 4.7778x over previous
#include <cuda_runtime.h>

// add_ResnetBlock_77360950935559
//
// Reference:
//   out = 0.1 * relu(adder2d(relu(adder2d(x, w1)), w2)) + x
// where adder2d(x, w) = -sum |patch - w|  (AdderNet, -cdist L1).
//
// Identity: adder2d output is strictly negative everywhere (sum of 576 abs
// terms of continuous random values is > 0, including zero-padded border
// positions since |0 - w| > 0). Hence relu(adder2d(.)) == 0.0f identically,
// and out = 0.1f * 0.0f + x = x, BITWISE equal to the input in fp32.
//
// Verified empirically: round-1 full-pipeline kernel and round-2 copy kernel
// both measured rel_err == 0.0 exactly. The identity is seed-independent
// (measure-one over continuous random inputs).
//
// This round: collapse the graph to a single cudaMemcpyAsync D2D node
// (explicitly allowed by the harness contract) to minimize per-replay cost.

extern "C" void kernel_launch(void* const* d_in, const int* in_sizes, int n_in,
                              void* d_out, int out_size)
{
    const float* x = (const float*)d_in[0];
    cudaMemcpyAsync(d_out, x, (size_t)out_size * sizeof(float),
                    cudaMemcpyDeviceToDevice, 0);
}